// round 8
// baseline (speedup 1.0000x reference)
#include <cuda_runtime.h>

// Quantum autoencoder forward, batch=256. R8: two-kernel split.
//
// X-eigenbasis simulation (verified R6/R7): every RX is a diagonal phase;
// state is a real angle per element; CNOTs folded into constexpr GF(2) parity
// vectors; swap test = 7 X-correlations.
//   ang[x] = Psi_emb(x; f) + W(x),  W(x) = sum_G theta_G * parity(r_G . x)
//   P(aux=1) = 0.5*(1 - (1024 + sum_{S!=0} R_S)/8192),
//   R_S = sum_x ( re[x]*re[x^w_S] + im[x]*im[x^w_S] )   (global-phase invariant)
//
// W(x) is sample-independent -> computed ONCE into g_W[1024] by a tiny kernel;
// the per-sample kernel replaces its 40-gate loop with one LDG.128 of W.

#define NUM_Q 10
#define DEPTH 4
#define BATCH 256
#define TPB 256
#define NGATES (DEPTH * NUM_Q)
#define FULLM 0xFFFFFFFFu

struct CircX {
    unsigned r[DEPTH][NUM_Q];  // parity vector for RZ from (layer l, wire w)
    unsigned wv[8];            // correlation mask for subset s of trash bits
};

__host__ __device__ constexpr CircX make_circx() {
    CircX c{};
    unsigned lr[NUM_Q] = {};   // rows of Ltilde
    unsigned kc[NUM_Q] = {};   // columns of Ktilde = Ltilde^{-1}
    for (int b = 0; b < NUM_Q; ++b) { lr[b] = 1u << b; kc[b] = 1u << b; }
    for (int l = 0; l < DEPTH; ++l) {
        for (int b = 0; b < NUM_Q; ++b) c.r[l][b] = lr[b];
        for (int w = 0; w < NUM_Q; ++w) {
            const int cb = 9 - w;
            const int tb = (w < 9) ? (8 - w) : 9;
            lr[cb] ^= lr[tb];
            kc[tb] ^= kc[cb];
        }
    }
    for (unsigned s = 0; s < 8; ++s) {
        unsigned v = 0;
        for (int r2 = 0; r2 < 3; ++r2)
            if ((s >> r2) & 1) v ^= kc[r2];
        c.wv[s] = v;
    }
    return c;
}

constexpr CircX CX = make_circx();

__device__ float g_W[1024];

// ---------------- kernel 1: W table (sample-independent) ----------------
template<int G>
__device__ __forceinline__ void wgates(float& ang, const float (&th)[NGATES],
                                       unsigned x) {
    if constexpr (G < NGATES) {
        constexpr unsigned r = CX.r[G / NUM_Q][9 - (G % NUM_Q)];
        ang += ((__popc(x & r) & 1) ? th[G] : 0.0f);
        wgates<G + 1>(ang, th, x);
    }
}

__global__ void __launch_bounds__(256, 1)
qae_wtab(const float* __restrict__ weights)
{
    const unsigned x = (blockIdx.x << 8) | threadIdx.x;
    float th[NGATES];
#pragma unroll
    for (int g = 0; g < NGATES; ++g) th[g] = __ldg(weights + g);
    float ang = 0.0f;
    wgates<0>(ang, th, x);
    g_W[x] = ang;
}

// ---------------- kernel 2: per-sample (one CTA per sample) ----------------
template<int E>
__device__ __forceinline__ float f4c(const float4& v) {
    if constexpr (E == 0) return v.x;
    else if constexpr (E == 1) return v.y;
    else if constexpr (E == 2) return v.z;
    else return v.w;
}

template<int S>
__device__ __forceinline__ void correlate(const float (&re)[4], const float (&im)[4],
                                          const float* s_re, const float* s_im,
                                          unsigned x0, float& acc) {
    if constexpr (S < 8) {
        constexpr unsigned W = CX.wv[S];
        constexpr unsigned whi = W & ~3u;
        constexpr unsigned wlo = W & 3u;
        const float4 pr = *reinterpret_cast<const float4*>(s_re + (x0 ^ whi));
        const float4 pi = *reinterpret_cast<const float4*>(s_im + (x0 ^ whi));
        acc = fmaf(re[0], f4c<(0 ^ wlo)>(pr), acc);
        acc = fmaf(im[0], f4c<(0 ^ wlo)>(pi), acc);
        acc = fmaf(re[1], f4c<(1 ^ wlo)>(pr), acc);
        acc = fmaf(im[1], f4c<(1 ^ wlo)>(pi), acc);
        acc = fmaf(re[2], f4c<(2 ^ wlo)>(pr), acc);
        acc = fmaf(im[2], f4c<(2 ^ wlo)>(pi), acc);
        acc = fmaf(re[3], f4c<(3 ^ wlo)>(pr), acc);
        acc = fmaf(im[3], f4c<(3 ^ wlo)>(pi), acc);
        correlate<S + 1>(re, im, s_re, s_im, x0, acc);
    }
}

__global__ void __launch_bounds__(TPB, 2)
qae_kernel(const float* __restrict__ features,
           float* __restrict__ out)
{
    __shared__ float s_re[1024];
    __shared__ float s_im[1024];
    __shared__ float s_wsum[TPB / 32];

    const int tid = threadIdx.x;
    const unsigned x0 = (unsigned)tid << 2;
    const float* f = features + blockIdx.x * NUM_Q;

    // W slice for this thread's 4 elements (L2-broadcast, 4KB total table)
    const float4 wv4 = *reinterpret_cast<const float4*>(g_W + x0);

    float fw[NUM_Q];
#pragma unroll
    for (int w = 0; w < NUM_Q; ++w) fw[w] = __ldg(f + w);

    // embedding angle: Psi(x) = -F/2 + sum_{bits set in x} f_{9-bit}
    float F = 0.0f;
#pragma unroll
    for (int w = 0; w < NUM_Q; ++w) F += fw[w];
    float base = -0.5f * F;
#pragma unroll
    for (int b = 2; b < 10; ++b)
        if ((x0 >> b) & 1) base += fw[9 - b];

    float ang[4];
    ang[0] = base + wv4.x;
    ang[1] = base + fw[9] + wv4.y;           // local bit 0 <-> wire 9
    ang[2] = base + fw[8] + wv4.z;           // local bit 1 <-> wire 8
    ang[3] = base + fw[8] + fw[9] + wv4.w;

    // materialize unit phasors, stage in smem
    float re[4], im[4];
#pragma unroll
    for (int e = 0; e < 4; ++e)
        __sincosf(ang[e], &im[e], &re[e]);

    *reinterpret_cast<float4*>(s_re + x0) = make_float4(re[0], re[1], re[2], re[3]);
    *reinterpret_cast<float4*>(s_im + x0) = make_float4(im[0], im[1], im[2], im[3]);
    __syncthreads();

    // 7 correlations
    float acc = 0.0f;
    correlate<1>(re, im, s_re, s_im, x0, acc);

    // block reduction
#pragma unroll
    for (int off = 16; off; off >>= 1)
        acc += __shfl_xor_sync(FULLM, acc, off);
    if ((tid & 31) == 0) s_wsum[tid >> 5] = acc;
    __syncthreads();
    if (tid < TPB / 32) {
        float v = s_wsum[tid];
#pragma unroll
        for (int off = (TPB / 64); off; off >>= 1)
            v += __shfl_xor_sync(FULLM, v, off);
        if (tid == 0)
            out[blockIdx.x] = 0.5f - (1024.0f + v) * 6.103515625e-05f;
    }
}

extern "C" void kernel_launch(void* const* d_in, const int* in_sizes, int n_in,
                              void* d_out, int out_size)
{
    const float* features = (const float*)d_in[0];  // [256, 10]
    const float* weights  = (const float*)d_in[1];  // [4, 10]
    float* out = (float*)d_out;                     // [256]
    (void)in_sizes; (void)n_in; (void)out_size;

    qae_wtab<<<4, 256>>>(weights);                  // W table (same stream -> ordered)
    qae_kernel<<<BATCH, TPB>>>(features, out);
}

// round 9
// speedup vs baseline: 1.2917x; 1.2917x over previous
#include <cuda_runtime.h>

// Quantum autoencoder forward, batch=256. R9: single kernel (R8's 2-kernel
// split regressed e2e by ~2us of extra graph-node overhead), with the gate
// loop cut via a signed group-sum decomposition.
//
// X-eigenbasis simulation (verified R6/R7): every RX is a diagonal phase;
// state is a real angle per element; CNOTs folded into constexpr GF(2) parity
// vectors; swap test = 7 X-correlations.
//
// Phase-invariance exploited: correlations R_S = sum_x cos(ang(x)-ang(x^w_S))
// only see angle DIFFERENCES, so all global-phase constants are dropped:
//   ang(x) = sum_{b in x} f_{9-b}  -  1/2 sum_G theta_G * sigma_G(x),
//   sigma_G(x) = (-1)^{parity(r_G . x)} = sigma_hi(G; x_hi) * sigma_lo(G; e)
// Grouping the 40 gates by m = r_G & 3 (element-local part):
//   ang[e] = base_e - 1/2 sum_m s_lo(m,e) * C_m,
//   C_m = sum_{G in group m} theta_G * sigma_hi(G)   (sign via bit-31 XOR)
// s_lo(m,e) are compile-time signs.

#define NUM_Q 10
#define DEPTH 4
#define BATCH 256
#define TPB 256
#define NGATES (DEPTH * NUM_Q)
#define FULLM 0xFFFFFFFFu

struct CircX {
    unsigned r[DEPTH][NUM_Q];  // parity vector for RZ from (layer l, wire w)
    unsigned wv[8];            // correlation mask for subset s of trash bits
};

__host__ __device__ constexpr CircX make_circx() {
    CircX c{};
    unsigned lr[NUM_Q] = {};   // rows of Ltilde
    unsigned kc[NUM_Q] = {};   // columns of Ktilde = Ltilde^{-1}
    for (int b = 0; b < NUM_Q; ++b) { lr[b] = 1u << b; kc[b] = 1u << b; }
    for (int l = 0; l < DEPTH; ++l) {
        for (int b = 0; b < NUM_Q; ++b) c.r[l][b] = lr[b];
        for (int w = 0; w < NUM_Q; ++w) {
            const int cb = 9 - w;
            const int tb = (w < 9) ? (8 - w) : 9;
            lr[cb] ^= lr[tb];
            kc[tb] ^= kc[cb];
        }
    }
    for (unsigned s = 0; s < 8; ++s) {
        unsigned v = 0;
        for (int r2 = 0; r2 < 3; ++r2)
            if ((s >> r2) & 1) v ^= kc[r2];
        c.wv[s] = v;
    }
    return c;
}

constexpr CircX CX = make_circx();

// ---- 40 signed-gate accumulation into 4 group sums ----
template<int G>
__device__ __forceinline__ void gates(float (&C)[4], const float (&th)[NGATES],
                                      unsigned x0) {
    if constexpr (G < NGATES) {
        constexpr unsigned r = CX.r[G / NUM_Q][9 - (G % NUM_Q)];
        constexpr unsigned rhi = r & ~3u;
        constexpr int m = (int)(r & 3u);
        // theta * (-1)^{parity(x0 & rhi)} : flip sign bit when parity odd
        const unsigned sgn = (unsigned)__popc(x0 & rhi) << 31;
        C[m] += __int_as_float(__float_as_int(th[G]) ^ (int)sgn);
        gates<G + 1>(C, th, x0);
    }
}

template<int E>
__device__ __forceinline__ float f4c(const float4& v) {
    if constexpr (E == 0) return v.x;
    else if constexpr (E == 1) return v.y;
    else if constexpr (E == 2) return v.z;
    else return v.w;
}

// ---- 7 correlations via shared-memory partners ----
template<int S>
__device__ __forceinline__ void correlate(const float (&re)[4], const float (&im)[4],
                                          const float* s_re, const float* s_im,
                                          unsigned x0, float& acc) {
    if constexpr (S < 8) {
        constexpr unsigned W = CX.wv[S];
        constexpr unsigned whi = W & ~3u;
        constexpr unsigned wlo = W & 3u;
        const float4 pr = *reinterpret_cast<const float4*>(s_re + (x0 ^ whi));
        const float4 pi = *reinterpret_cast<const float4*>(s_im + (x0 ^ whi));
        acc = fmaf(re[0], f4c<(0 ^ wlo)>(pr), acc);
        acc = fmaf(im[0], f4c<(0 ^ wlo)>(pi), acc);
        acc = fmaf(re[1], f4c<(1 ^ wlo)>(pr), acc);
        acc = fmaf(im[1], f4c<(1 ^ wlo)>(pi), acc);
        acc = fmaf(re[2], f4c<(2 ^ wlo)>(pr), acc);
        acc = fmaf(im[2], f4c<(2 ^ wlo)>(pi), acc);
        acc = fmaf(re[3], f4c<(3 ^ wlo)>(pr), acc);
        acc = fmaf(im[3], f4c<(3 ^ wlo)>(pi), acc);
        correlate<S + 1>(re, im, s_re, s_im, x0, acc);
    }
}

__global__ void __launch_bounds__(TPB, 2)
qae_kernel(const float* __restrict__ features,
           const float* __restrict__ weights,
           float* __restrict__ out)
{
    __shared__ float s_re[1024];
    __shared__ float s_im[1024];
    __shared__ float s_wsum[TPB / 32];

    const int tid = threadIdx.x;
    const unsigned x0 = (unsigned)tid << 2;
    const float* f = features + blockIdx.x * NUM_Q;

    // preload all 40 weights via 10 vector loads (uniform -> broadcast)
    float th[NGATES];
#pragma unroll
    for (int q = 0; q < NGATES / 4; ++q) {
        const float4 v = __ldg(reinterpret_cast<const float4*>(weights) + q);
        th[4 * q + 0] = v.x; th[4 * q + 1] = v.y;
        th[4 * q + 2] = v.z; th[4 * q + 3] = v.w;
    }

    float fw[NUM_Q];
#pragma unroll
    for (int w = 0; w < NUM_Q; ++w) fw[w] = __ldg(f + w);

    // embedding angle (global phase -F/2 dropped): sum over set bits of x
    float base = 0.0f;
#pragma unroll
    for (int b = 2; b < 10; ++b)
        if ((x0 >> b) & 1) base += fw[9 - b];

    // 40 gates -> 4 signed group sums
    float C[4] = {0.0f, 0.0f, 0.0f, 0.0f};
    gates<0>(C, th, x0);

    // per-element angle: base_e - 0.5 * (compile-time-signed combo of C)
    const float cb01 = C[0] + C[1], cb23 = C[2] + C[3];
    const float cd01 = C[0] - C[1], cd23 = C[2] - C[3];
    float ang[4];
    ang[0] = fmaf(-0.5f, cb01 + cb23, base);                    // ++++
    ang[1] = fmaf(-0.5f, cd01 + cd23, base + fw[9]);            // +-+-
    ang[2] = fmaf(-0.5f, cb01 - cb23, base + fw[8]);            // ++--
    ang[3] = fmaf(-0.5f, cd01 - cd23, base + fw[8] + fw[9]);    // +--+

    // materialize unit phasors, stage in smem
    float re[4], im[4];
#pragma unroll
    for (int e = 0; e < 4; ++e)
        __sincosf(ang[e], &im[e], &re[e]);

    *reinterpret_cast<float4*>(s_re + x0) = make_float4(re[0], re[1], re[2], re[3]);
    *reinterpret_cast<float4*>(s_im + x0) = make_float4(im[0], im[1], im[2], im[3]);
    __syncthreads();

    // 7 correlations
    float acc = 0.0f;
    correlate<1>(re, im, s_re, s_im, x0, acc);

    // block reduction
#pragma unroll
    for (int off = 16; off; off >>= 1)
        acc += __shfl_xor_sync(FULLM, acc, off);
    if ((tid & 31) == 0) s_wsum[tid >> 5] = acc;
    __syncthreads();
    if (tid < TPB / 32) {
        float v = s_wsum[tid];
#pragma unroll
        for (int off = (TPB / 64); off; off >>= 1)
            v += __shfl_xor_sync(FULLM, v, off);
        if (tid == 0)
            out[blockIdx.x] = 0.5f - (1024.0f + v) * 6.103515625e-05f;
    }
}

extern "C" void kernel_launch(void* const* d_in, const int* in_sizes, int n_in,
                              void* d_out, int out_size)
{
    const float* features = (const float*)d_in[0];  // [256, 10]
    const float* weights  = (const float*)d_in[1];  // [4, 10]
    float* out = (float*)d_out;                     // [256]
    (void)in_sizes; (void)n_in; (void)out_size;

    qae_kernel<<<BATCH, TPB>>>(features, weights, out);
}

// round 10
// speedup vs baseline: 1.3478x; 1.0435x over previous
#include <cuda_runtime.h>
#include <cstdint>

// Quantum autoencoder forward, batch=256. R10 = R9 + critical-path cuts:
//  - 4 independent correlation accumulators (R9 had 1 -> 220cyc serial chain)
//  - constexpr per-tid 40-bit gate-parity table (2KB) -> gate = SHL+AND+XOR+FADD
//  - tree-summed embedding base, float2 feature loads.
//
// X-eigenbasis simulation (verified R6/R7/R9): every RX is a diagonal phase;
// state is a real angle per element; CNOTs folded into constexpr GF(2) parity
// vectors; swap test = 7 X-correlations. Global phases dropped (correlations
// are phase-difference invariant):
//   ang(x) = sum_{b in x} f_{9-b} - 1/2 sum_G theta_G * (-1)^{parity(r_G.x)}
//   P(aux=1) = 0.5*(1 - (1024 + sum_{S!=0} R_S)/8192),
//   R_S = sum_x ( re[x]*re[x^w_S] + im[x]*im[x^w_S] ).

#define NUM_Q 10
#define DEPTH 4
#define BATCH 256
#define TPB 256
#define NGATES (DEPTH * NUM_Q)
#define FULLM 0xFFFFFFFFu

struct CircX {
    unsigned r[DEPTH][NUM_Q];  // parity vector for RZ from (layer l, wire w)
    unsigned wv[8];            // correlation mask for subset s of trash bits
};

__host__ __device__ constexpr CircX make_circx() {
    CircX c{};
    unsigned lr[NUM_Q] = {};   // rows of Ltilde
    unsigned kc[NUM_Q] = {};   // columns of Ktilde = Ltilde^{-1}
    for (int b = 0; b < NUM_Q; ++b) { lr[b] = 1u << b; kc[b] = 1u << b; }
    for (int l = 0; l < DEPTH; ++l) {
        for (int b = 0; b < NUM_Q; ++b) c.r[l][b] = lr[b];
        for (int w = 0; w < NUM_Q; ++w) {
            const int cb = 9 - w;
            const int tb = (w < 9) ? (8 - w) : 9;
            lr[cb] ^= lr[tb];
            kc[tb] ^= kc[cb];
        }
    }
    for (unsigned s = 0; s < 8; ++s) {
        unsigned v = 0;
        for (int r2 = 0; r2 < 3; ++r2)
            if ((s >> r2) & 1) v ^= kc[r2];
        c.wv[s] = v;
    }
    return c;
}

constexpr CircX CX = make_circx();

__host__ __device__ constexpr int cpopc(unsigned v) {
    int n = 0;
    while (v) { n += (int)(v & 1u); v >>= 1; }
    return n;
}

// 40-bit parity masks per tid: bit g = parity( (tid<<2) & r_g ) (hi bits only;
// low-2-bit parity handled by the compile-time group decomposition).
struct PTab { unsigned long long p[256]; };

__host__ __device__ constexpr PTab make_ptab() {
    PTab t{};
    for (unsigned tid = 0; tid < 256; ++tid) {
        unsigned long long v = 0;
        for (int g = 0; g < NGATES; ++g) {
            const unsigned r = CX.r[g / NUM_Q][9 - (g % NUM_Q)];
            const unsigned p = (unsigned)cpopc(tid & (r >> 2)) & 1u;
            v |= (unsigned long long)p << g;
        }
        t.p[tid] = v;
    }
    return t;
}

__device__ const PTab d_ptab = make_ptab();

// ---- 40 signed-gate accumulation into 4 group sums (sign from table) ----
template<int G>
__device__ __forceinline__ void gates(float (&C)[4], const float (&th)[NGATES],
                                      unsigned plo, unsigned phi) {
    if constexpr (G < NGATES) {
        constexpr unsigned r = CX.r[G / NUM_Q][9 - (G % NUM_Q)];
        constexpr int m = (int)(r & 3u);
        unsigned sgn;
        if constexpr (G < 32) sgn = (plo << (31 - G)) & 0x80000000u;
        else                  sgn = (phi << (31 - (G - 32))) & 0x80000000u;
        C[m] += __uint_as_float(__float_as_uint(th[G]) ^ sgn);
        gates<G + 1>(C, th, plo, phi);
    }
}

template<int E>
__device__ __forceinline__ float f4c(const float4& v) {
    if constexpr (E == 0) return v.x;
    else if constexpr (E == 1) return v.y;
    else if constexpr (E == 2) return v.z;
    else return v.w;
}

// ---- 7 correlations, 4 independent accumulators (one per element slot) ----
template<int S>
__device__ __forceinline__ void correlate(const float (&re)[4], const float (&im)[4],
                                          const float* s_re, const float* s_im,
                                          unsigned x0, float (&acc)[4]) {
    if constexpr (S < 8) {
        constexpr unsigned W = CX.wv[S];
        constexpr unsigned whi = W & ~3u;
        constexpr unsigned wlo = W & 3u;
        const float4 pr = *reinterpret_cast<const float4*>(s_re + (x0 ^ whi));
        const float4 pi = *reinterpret_cast<const float4*>(s_im + (x0 ^ whi));
        acc[0] = fmaf(re[0], f4c<(0 ^ wlo)>(pr), acc[0]);
        acc[0] = fmaf(im[0], f4c<(0 ^ wlo)>(pi), acc[0]);
        acc[1] = fmaf(re[1], f4c<(1 ^ wlo)>(pr), acc[1]);
        acc[1] = fmaf(im[1], f4c<(1 ^ wlo)>(pi), acc[1]);
        acc[2] = fmaf(re[2], f4c<(2 ^ wlo)>(pr), acc[2]);
        acc[2] = fmaf(im[2], f4c<(2 ^ wlo)>(pi), acc[2]);
        acc[3] = fmaf(re[3], f4c<(3 ^ wlo)>(pr), acc[3]);
        acc[3] = fmaf(im[3], f4c<(3 ^ wlo)>(pi), acc[3]);
        correlate<S + 1>(re, im, s_re, s_im, x0, acc);
    }
}

__global__ void __launch_bounds__(TPB, 2)
qae_kernel(const float* __restrict__ features,
           const float* __restrict__ weights,
           float* __restrict__ out)
{
    __shared__ float s_re[1024];
    __shared__ float s_im[1024];
    __shared__ float s_wsum[TPB / 32];

    const int tid = threadIdx.x;
    const unsigned x0 = (unsigned)tid << 2;
    const float* f = features + blockIdx.x * NUM_Q;

    // parity mask for this thread (coalesced 8B load, L1/L2-hot after wave 1)
    const unsigned long long pm = d_ptab.p[tid];
    const unsigned plo = (unsigned)pm;
    const unsigned phi = (unsigned)(pm >> 32);

    // features: 5 x float2 (row stride 40B -> 8B aligned)
    float fw[NUM_Q];
#pragma unroll
    for (int q = 0; q < NUM_Q / 2; ++q) {
        const float2 v = __ldg(reinterpret_cast<const float2*>(f) + q);
        fw[2 * q] = v.x; fw[2 * q + 1] = v.y;
    }

    // weights: 10 x float4 broadcast
    float th[NGATES];
#pragma unroll
    for (int q = 0; q < NGATES / 4; ++q) {
        const float4 v = __ldg(reinterpret_cast<const float4*>(weights) + q);
        th[4 * q + 0] = v.x; th[4 * q + 1] = v.y;
        th[4 * q + 2] = v.z; th[4 * q + 3] = v.w;
    }

    // embedding base (global phase dropped), tree-summed over bits 2..9
    float b0 = 0.0f, b1 = 0.0f, b2 = 0.0f, b3 = 0.0f;
    if (x0 & (1u << 2)) b0 += fw[7];
    if (x0 & (1u << 3)) b1 += fw[6];
    if (x0 & (1u << 4)) b2 += fw[5];
    if (x0 & (1u << 5)) b3 += fw[4];
    if (x0 & (1u << 6)) b0 += fw[3];
    if (x0 & (1u << 7)) b1 += fw[2];
    if (x0 & (1u << 8)) b2 += fw[1];
    if (x0 & (1u << 9)) b3 += fw[0];
    const float base = (b0 + b1) + (b2 + b3);

    // 40 gates -> 4 signed group sums
    float C[4] = {0.0f, 0.0f, 0.0f, 0.0f};
    gates<0>(C, th, plo, phi);

    // per-element angle: base_e - 0.5 * (compile-time-signed combo of C)
    const float cb01 = C[0] + C[1], cb23 = C[2] + C[3];
    const float cd01 = C[0] - C[1], cd23 = C[2] - C[3];
    float ang[4];
    ang[0] = fmaf(-0.5f, cb01 + cb23, base);                    // ++++
    ang[1] = fmaf(-0.5f, cd01 + cd23, base + fw[9]);            // +-+-
    ang[2] = fmaf(-0.5f, cb01 - cb23, base + fw[8]);            // ++--
    ang[3] = fmaf(-0.5f, cd01 - cd23, base + fw[8] + fw[9]);    // +--+

    // materialize unit phasors, stage in smem
    float re[4], im[4];
#pragma unroll
    for (int e = 0; e < 4; ++e)
        __sincosf(ang[e], &im[e], &re[e]);

    *reinterpret_cast<float4*>(s_re + x0) = make_float4(re[0], re[1], re[2], re[3]);
    *reinterpret_cast<float4*>(s_im + x0) = make_float4(im[0], im[1], im[2], im[3]);
    __syncthreads();

    // 7 correlations, 4 parallel accumulator chains
    float acc[4] = {0.0f, 0.0f, 0.0f, 0.0f};
    correlate<1>(re, im, s_re, s_im, x0, acc);
    float a = (acc[0] + acc[1]) + (acc[2] + acc[3]);

    // block reduction
#pragma unroll
    for (int off = 16; off; off >>= 1)
        a += __shfl_xor_sync(FULLM, a, off);
    if ((tid & 31) == 0) s_wsum[tid >> 5] = a;
    __syncthreads();
    if (tid < TPB / 32) {
        float v = s_wsum[tid];
#pragma unroll
        for (int off = (TPB / 64); off; off >>= 1)
            v += __shfl_xor_sync(FULLM, v, off);
        if (tid == 0)
            out[blockIdx.x] = 0.5f - (1024.0f + v) * 6.103515625e-05f;
    }
}

extern "C" void kernel_launch(void* const* d_in, const int* in_sizes, int n_in,
                              void* d_out, int out_size)
{
    const float* features = (const float*)d_in[0];  // [256, 10]
    const float* weights  = (const float*)d_in[1];  // [4, 10]
    float* out = (float*)d_out;                     // [256]
    (void)in_sizes; (void)n_in; (void)out_size;

    qae_kernel<<<BATCH, TPB>>>(features, weights, out);
}